// round 4
// baseline (speedup 1.0000x reference)
#include <cuda_runtime.h>
#include <math.h>

#define M 768
#define PAIR_THREADS 256
#define NB ((M * M) / PAIR_THREADS)   // 589824/256 = 2304, exact

// Scratch in __device__ globals (no allocations allowed).
__device__ float g_cor[M][8];      // corner coords x0,y0,...,x3,y3 (CCW)
__device__ float g_cx[M], g_cy[M];
__device__ float g_area[M];
__device__ float g_rad[M];         // half-diagonal
__device__ float g_partial[NB][2]; // per-block (repel_sum, iou_sum)
__device__ float g_size_sum;

// ---------------------------------------------------------------------------
// Kernel A: per-box prep + size loss (1 block, 768 threads, deterministic)
// ---------------------------------------------------------------------------
__global__ void prep_kernel(const float* __restrict__ pred) {
    int i = threadIdx.x;
    float pen = 0.f;
    if (i < M) {
        const float* p = pred + i * 6;
        float cx = p[0], cy = p[1], w = p[2], h = p[3], c = p[4], s = p[5];
        float hw = 0.5f * w, hh = 0.5f * h;
        // local corners CCW: (-hw,-hh),(hw,-hh),(hw,hh),(-hw,hh)
        float dxs[4] = {-hw, hw, hw, -hw};
        float dys[4] = {-hh, -hh, hh, hh};
#pragma unroll
        for (int k = 0; k < 4; k++) {
            g_cor[i][2 * k]     = cx + c * dxs[k] - s * dys[k];
            g_cor[i][2 * k + 1] = cy + s * dxs[k] + c * dys[k];
        }
        g_cx[i] = cx; g_cy[i] = cy;
        g_area[i] = w * h;
        g_rad[i] = 0.5f * sqrtf(w * w + h * h);
        pen = fmaxf(0.02f - w, 0.f) + fmaxf(0.02f - h, 0.f);
    }
    __shared__ float sh[768];
    sh[i] = pen;
    __syncthreads();
    if (i < 256) sh[i] += sh[i + 512];
    __syncthreads();
    if (i < 256) sh[i] += sh[i + 256];
    __syncthreads();
    for (int off = 128; off > 0; off >>= 1) {
        if (i < off) sh[i] += sh[i + off];
        __syncthreads();
    }
    if (i == 0) g_size_sum = sh[0];
}

// ---------------------------------------------------------------------------
// Kernel B: all (i,j) pairs, i<j active, distance reject + SH clip
// ---------------------------------------------------------------------------
__global__ void pair_kernel() {
    int k = blockIdx.x * blockDim.x + threadIdx.x;
    int i = k / M;
    int j = k - i * M;

    float repel = 0.f;
    float iouv  = 0.f;

    if (i < j) {
        float dx = g_cx[i] - g_cx[j];
        float dy = g_cy[i] - g_cy[j];
        float dist = sqrtf(dx * dx + dy * dy);
        repel = 2.f * fmaxf(0.08f - dist, 0.f);

        if (dist < g_rad[i] + g_rad[j]) {
            // Sutherland–Hodgman: clip quad i against the 4 half-planes of quad j.
            float px[8], py[8], qx[8], qy[8];
#pragma unroll
            for (int t = 0; t < 4; t++) {
                px[t] = g_cor[i][2 * t];
                py[t] = g_cor[i][2 * t + 1];
            }
            int n = 4;
#pragma unroll
            for (int e = 0; e < 4; e++) {
                int e1 = (e + 1) & 3;
                float q0x = g_cor[j][2 * e],  q0y = g_cor[j][2 * e + 1];
                float ex  = g_cor[j][2 * e1] - q0x;
                float ey  = g_cor[j][2 * e1 + 1] - q0y;
                int m2 = 0;
                for (int t = 0; t < n; t++) {
                    int t1 = (t + 1 == n) ? 0 : t + 1;
                    float dc = ex * (py[t]  - q0y) - ey * (px[t]  - q0x);
                    float dn = ex * (py[t1] - q0y) - ey * (px[t1] - q0x);
                    bool inc = (dc >= 0.f), inn = (dn >= 0.f);
                    if (inc) { qx[m2] = px[t]; qy[m2] = py[t]; m2++; }
                    if (inc != inn) {
                        float tt = dc / (dc - dn);
                        qx[m2] = px[t] + tt * (px[t1] - px[t]);
                        qy[m2] = py[t] + tt * (py[t1] - py[t]);
                        m2++;
                    }
                }
                n = m2;
                if (n == 0) break;
                for (int t = 0; t < n; t++) { px[t] = qx[t]; py[t] = qy[t]; }
            }
            float inter = 0.f;
            if (n >= 3) {
                float acc = 0.f;
                for (int t = 0; t < n; t++) {
                    int t1 = (t + 1 == n) ? 0 : t + 1;
                    acc += px[t] * py[t1] - px[t1] * py[t];
                }
                inter = 0.5f * fabsf(acc);
            }
            float uni = g_area[i] + g_area[j] - inter;
            float iou = inter / fmaxf(uni, 1e-12f);
            iouv = 2.f * fmaxf(iou - 0.1f, 0.f);
        }
    }

    // Fixed-order block reduction (deterministic).
    __shared__ float s1[PAIR_THREADS], s2[PAIR_THREADS];
    int t = threadIdx.x;
    s1[t] = repel; s2[t] = iouv;
    __syncthreads();
    for (int off = PAIR_THREADS / 2; off > 0; off >>= 1) {
        if (t < off) { s1[t] += s1[t + off]; s2[t] += s2[t + off]; }
        __syncthreads();
    }
    if (t == 0) {
        g_partial[blockIdx.x][0] = s1[0];
        g_partial[blockIdx.x][1] = s2[0];
    }
}

// ---------------------------------------------------------------------------
// Kernel C: combine (deterministic fixed-order sum of partials)
// ---------------------------------------------------------------------------
__global__ void finish_kernel(float* __restrict__ out, int out_size) {
    __shared__ float s1[256], s2[256];
    int t = threadIdx.x;
    float r = 0.f, v = 0.f;
    for (int b = t; b < NB; b += 256) {
        r += g_partial[b][0];
        v += g_partial[b][1];
    }
    s1[t] = r; s2[t] = v;
    __syncthreads();
    for (int off = 128; off > 0; off >>= 1) {
        if (t < off) { s1[t] += s1[t + off]; s2[t] += s2[t + off]; }
        __syncthreads();
    }
    __syncthreads();
    if (t == 0) {
        float total = s1[0] / (float)(M * (M - 1))
                    + g_size_sum / (float)M
                    + s2[0] / (float)(M * M);
        s1[0] = total;
    }
    __syncthreads();
    float total = s1[0];
    for (int o = t; o < out_size; o += 256) out[o] = total;
}

extern "C" void kernel_launch(void* const* d_in, const int* in_sizes, int n_in,
                              void* d_out, int out_size) {
    const float* pred = (const float*)d_in[0];
    float* out = (float*)d_out;
    prep_kernel<<<1, 768>>>(pred);
    pair_kernel<<<NB, PAIR_THREADS>>>();
    finish_kernel<<<1, 256>>>(out, out_size);
}

// round 6
// speedup vs baseline: 1.5334x; 1.5334x over previous
#include <cuda_runtime.h>
#include <math.h>

#define M      768
#define N1     767          // M-1 (odd)
#define HALF   384          // M/2
#define NPAIR  (N1 * HALF)  // 294528 unique pairs
#define TPB    256
#define NBLK   ((NPAIR + TPB - 1) / TPB)   // 1151

__device__ float g_partial[NBLK][2];  // (repel_sum, iou_sum) per block
__device__ int   g_count;             // zero at load; reset by finalize

// Clip one directed edge (global endpoints g0->g1, local-frame endpoints
// l0->l1 in the clipping box's frame) against the axis-aligned box
// |x|<=hw, |y|<=hh. Returns cross(pa, pb) of the clipped segment in the
// GLOBAL frame (t parameters are frame-invariant). 0 if empty.
__device__ __forceinline__ float clip_contrib(
    float g0x, float g0y, float g1x, float g1y,
    float l0x, float l0y, float l1x, float l1y,
    float hw, float hh)
{
    float tlo = 0.f, thi = 1.f;
    bool empty = false;

#define CLIP_PLANE(D0, D1)                              \
    {                                                   \
        float d0 = (D0), d1 = (D1);                     \
        bool o0 = d0 < 0.f, o1 = d1 < 0.f;              \
        empty = empty || (o0 && o1);                    \
        float t = __fdividef(d0, d0 - d1);              \
        if (o0) tlo = fmaxf(tlo, t);                    \
        if (o1) thi = fminf(thi, t);                    \
    }

    CLIP_PLANE(hw - l0x, hw - l1x)   // x <=  hw
    CLIP_PLANE(hw + l0x, hw + l1x)   // x >= -hw
    CLIP_PLANE(hh - l0y, hh - l1y)   // y <=  hh
    CLIP_PLANE(hh + l0y, hh + l1y)   // y >= -hh
#undef CLIP_PLANE

    if (empty || tlo >= thi) return 0.f;
    float ex = g1x - g0x, ey = g1y - g0y;
    float ax = g0x + tlo * ex, ay = g0y + tlo * ey;
    float bx = g0x + thi * ex, by = g0y + thi * ey;
    return ax * by - ay * bx;
}

__global__ __launch_bounds__(TPB)
void fused_kernel(const float* __restrict__ pred, float* __restrict__ out,
                  int out_size)
{
    int k = blockIdx.x * TPB + threadIdx.x;
    float repel = 0.f, iouv = 0.f;

    if (k < NPAIR) {
        // Round-robin tournament schedule: each unordered pair exactly once.
        int r = k / HALF;
        int p = k - r * HALF;
        int ia, ib;
        if (p == 0) { ia = N1; ib = r; }
        else {
            ia = r + p;  if (ia >= N1) ia -= N1;
            ib = r - p;  if (ib < 0)   ib += N1;
        }

        const float* pa = pred + ia * 6;
        const float* pb = pred + ib * 6;
        float acx = __ldg(pa + 0), acy = __ldg(pa + 1);
        float aw  = __ldg(pa + 2), ah  = __ldg(pa + 3);
        float ac  = __ldg(pa + 4), as  = __ldg(pa + 5);
        float bcx = __ldg(pb + 0), bcy = __ldg(pb + 1);
        float bw  = __ldg(pb + 2), bh  = __ldg(pb + 3);
        float bc  = __ldg(pb + 4), bs  = __ldg(pb + 5);

        float dx = acx - bcx, dy = acy - bcy;
        float dist = sqrtf(dx * dx + dy * dy);
        repel = 2.f * fmaxf(0.08f - dist, 0.f);

        float haw = 0.5f * aw, hah = 0.5f * ah;
        float hbw = 0.5f * bw, hbh = 0.5f * bh;
        float radA = sqrtf(haw * haw + hah * hah);
        float radB = sqrtf(hbw * hbw + hbh * hbh);

        if (dist < radA + radB) {
            // Global corners (CCW): signs (-,-),(+,-),(+,+),(-,+)
            float gxA[4], gyA[4], gxB[4], gyB[4];
            float lxA[4], lyA[4], lxB[4], lyB[4];
            const float SX[4] = {-1.f, 1.f, 1.f, -1.f};
            const float SY[4] = {-1.f, -1.f, 1.f, 1.f};
#pragma unroll
            for (int t = 0; t < 4; t++) {
                float ux = SX[t] * haw, uy = SY[t] * hah;
                gxA[t] = acx + ac * ux - as * uy;
                gyA[t] = acy + as * ux + ac * uy;
                float vx = SX[t] * hbw, vy = SY[t] * hbh;
                gxB[t] = bcx + bc * vx - bs * vy;
                gyB[t] = bcy + bs * vx + bc * vy;
            }
            // A's corners in B's local frame; B's corners in A's frame.
#pragma unroll
            for (int t = 0; t < 4; t++) {
                float px = gxA[t] - bcx, py = gyA[t] - bcy;
                lxA[t] =  bc * px + bs * py;
                lyA[t] = -bs * px + bc * py;
                float qx = gxB[t] - acx, qy = gyB[t] - acy;
                lxB[t] =  ac * qx + as * qy;
                lyB[t] = -as * qx + ac * qy;
            }

            // Green's theorem over the intersection boundary:
            // A-edge pieces inside B  +  B-edge pieces inside A.
            float cs = 0.f;
#pragma unroll
            for (int e = 0; e < 4; e++) {
                int e1 = (e + 1) & 3;
                cs += clip_contrib(gxA[e], gyA[e], gxA[e1], gyA[e1],
                                   lxA[e], lyA[e], lxA[e1], lyA[e1],
                                   hbw, hbh);
            }
#pragma unroll
            for (int e = 0; e < 4; e++) {
                int e1 = (e + 1) & 3;
                cs += clip_contrib(gxB[e], gyB[e], gxB[e1], gyB[e1],
                                   lxB[e], lyB[e], lxB[e1], lyB[e1],
                                   haw, hah);
            }

            float inter = 0.5f * fabsf(cs);
            float uni = aw * ah + bw * bh - inter;
            float iou = __fdividef(inter, fmaxf(uni, 1e-12f));
            iouv = 2.f * fmaxf(iou - 0.1f, 0.f);
        }
    }

    // Deterministic fixed-order block reduction.
    __shared__ float s1[TPB], s2[TPB], s3[TPB];
    __shared__ bool last;
    int t = threadIdx.x;
    s1[t] = repel; s2[t] = iouv;
    __syncthreads();
#pragma unroll
    for (int off = TPB / 2; off > 0; off >>= 1) {
        if (t < off) { s1[t] += s1[t + off]; s2[t] += s2[t + off]; }
        __syncthreads();
    }
    if (t == 0) {
        g_partial[blockIdx.x][0] = s1[0];
        g_partial[blockIdx.x][1] = s2[0];
        __threadfence();
        int c = atomicAdd(&g_count, 1);
        last = (c == NBLK - 1);
    }
    __syncthreads();

    // Last arriving block: deterministic fixed-order final sum + size loss.
    if (last) {
        float r = 0.f, v = 0.f;
        for (int b = t; b < NBLK; b += TPB) {
            r += g_partial[b][0];
            v += g_partial[b][1];
        }
        float pen = 0.f;
        for (int i = t; i < M; i += TPB) {
            float w = __ldg(pred + i * 6 + 2);
            float h = __ldg(pred + i * 6 + 3);
            pen += fmaxf(0.02f - w, 0.f) + fmaxf(0.02f - h, 0.f);
        }
        s1[t] = r; s2[t] = v; s3[t] = pen;
        __syncthreads();
#pragma unroll
        for (int off = TPB / 2; off > 0; off >>= 1) {
            if (t < off) {
                s1[t] += s1[t + off];
                s2[t] += s2[t + off];
                s3[t] += s3[t + off];
            }
            __syncthreads();
        }
        if (t == 0) {
            float total = s1[0] / (float)(M * (M - 1))
                        + s3[0] / (float)M
                        + s2[0] / (float)(M * M);
            for (int o = 0; o < out_size; o++) out[o] = total;
            g_count = 0;   // re-arm for next graph replay
        }
    }
}

extern "C" void kernel_launch(void* const* d_in, const int* in_sizes, int n_in,
                              void* d_out, int out_size) {
    const float* pred = (const float*)d_in[0];
    float* out = (float*)d_out;
    fused_kernel<<<NBLK, TPB>>>(pred, out, out_size);
}

// round 7
// speedup vs baseline: 1.8941x; 1.2352x over previous
#include <cuda_runtime.h>
#include <math.h>

#define M      768
#define N1     767                 // M-1 (odd)
#define HALF   384                 // M/2
#define NPAIR  (N1 * HALF)         // 294528 unique pairs
#define TPB    256
#define NW     (TPB / 32)          // 8 warps
#define U      4                   // pair-chunks per thread
#define PPB    (TPB * U)           // 1024 pairs per block
#define NBLK   ((NPAIR + PPB - 1) / PPB)   // 288
#define QCAP   (U * 32)            // 128 queue slots per warp (worst case exact)

__device__ float g_partial[NBLK][2];  // (repel_sum, iou_sum) per block
__device__ int   g_count;             // zero-init; re-armed by finalize

// Clip directed edge (global g0->g1; same edge in the clipping box's local
// frame l0->l1) against axis-aligned box |x|<=hw,|y|<=hh. Returns
// cross(pa,pb) of the surviving segment in the GLOBAL frame (t is
// frame-invariant), 0 if the edge misses the box.
__device__ __forceinline__ float clip_contrib(
    float g0x, float g0y, float g1x, float g1y,
    float l0x, float l0y, float l1x, float l1y,
    float hw, float hh)
{
    float tlo = 0.f, thi = 1.f;
    bool empty = false;

#define CLIP_PLANE(D0, D1)                              \
    {                                                   \
        float d0 = (D0), d1 = (D1);                     \
        bool o0 = d0 < 0.f, o1 = d1 < 0.f;              \
        empty = empty || (o0 && o1);                    \
        float t = __fdividef(d0, d0 - d1);              \
        if (o0) tlo = fmaxf(tlo, t);                    \
        if (o1) thi = fminf(thi, t);                    \
    }

    CLIP_PLANE(hw - l0x, hw - l1x)
    CLIP_PLANE(hw + l0x, hw + l1x)
    CLIP_PLANE(hh - l0y, hh - l1y)
    CLIP_PLANE(hh + l0y, hh + l1y)
#undef CLIP_PLANE

    if (empty || tlo >= thi) return 0.f;
    float ex = g1x - g0x, ey = g1y - g0y;
    float ax = g0x + tlo * ex, ay = g0y + tlo * ey;
    float bx = g0x + thi * ex, by = g0y + thi * ey;
    return ax * by - ay * bx;
}

__device__ __forceinline__ void pair_from_k(int k, int& ia, int& ib)
{
    int r = k / HALF;
    int p = k - r * HALF;
    if (p == 0) { ia = N1; ib = r; }
    else {
        ia = r + p;  if (ia >= N1) ia -= N1;
        ib = r - p;  if (ib < 0)   ib += N1;
    }
}

__global__ __launch_bounds__(TPB)
void fused_kernel(const float* __restrict__ pred, float* __restrict__ out,
                  int out_size)
{
    __shared__ float spred[M * 6];        // 18 KB: full pred copy
    __shared__ float scx[M], scy[M], srad[M];
    __shared__ int   q[NW][QCAP];         // warp-private active-pair queues
    __shared__ float s1[TPB], s2[TPB], s3[TPB];
    __shared__ bool  last;

    const int tid  = threadIdx.x;
    const int wid  = tid >> 5;
    const int lane = tid & 31;

    // ---- stage pred + per-box derived values in shared ----
    for (int idx = tid; idx < M * 6; idx += TPB) spred[idx] = __ldg(pred + idx);
    __syncthreads();
    for (int i = tid; i < M; i += TPB) {
        float w = spred[i * 6 + 2], h = spred[i * 6 + 3];
        scx[i] = spred[i * 6 + 0];
        scy[i] = spred[i * 6 + 1];
        srad[i] = 0.5f * sqrtf(w * w + h * h);
    }
    __syncthreads();

    // ---- phase 1: distance test all pairs; repel; compact survivors ----
    const int base = blockIdx.x * PPB;
    float repel = 0.f;
    int nact = 0;
#pragma unroll
    for (int chunk = 0; chunk < U; chunk++) {
        int k = base + chunk * TPB + (wid << 5) + lane;
        bool active = false;
        if (k < NPAIR) {
            int ia, ib;
            pair_from_k(k, ia, ib);
            float dx = scx[ia] - scx[ib];
            float dy = scy[ia] - scy[ib];
            float dist = sqrtf(dx * dx + dy * dy);
            repel += 2.f * fmaxf(0.08f - dist, 0.f);
            active = dist < srad[ia] + srad[ib];
        }
        unsigned mask = __ballot_sync(0xFFFFFFFFu, active);
        if (active) {
            int rank = __popc(mask & ((1u << lane) - 1u));
            q[wid][nact + rank] = k;
        }
        nact += __popc(mask);
    }
    __syncwarp();

    // ---- phase 2: drain warp queue, all lanes useful ----
    float iouv = 0.f;
    for (int s = lane; s < nact; s += 32) {
        int ia, ib;
        pair_from_k(q[wid][s], ia, ib);
        const float* pa = spred + ia * 6;
        const float* pb = spred + ib * 6;
        float acx = pa[0], acy = pa[1], aw = pa[2], ah = pa[3], ac = pa[4], as = pa[5];
        float bcx = pb[0], bcy = pb[1], bw = pb[2], bh = pb[3], bc = pb[4], bs = pb[5];

        float haw = 0.5f * aw, hah = 0.5f * ah;
        float hbw = 0.5f * bw, hbh = 0.5f * bh;

        float gxA[4], gyA[4], gxB[4], gyB[4];
        float lxA[4], lyA[4], lxB[4], lyB[4];
        const float SX[4] = {-1.f, 1.f, 1.f, -1.f};
        const float SY[4] = {-1.f, -1.f, 1.f, 1.f};
#pragma unroll
        for (int t = 0; t < 4; t++) {
            float ux = SX[t] * haw, uy = SY[t] * hah;
            gxA[t] = acx + ac * ux - as * uy;
            gyA[t] = acy + as * ux + ac * uy;
            float vx = SX[t] * hbw, vy = SY[t] * hbh;
            gxB[t] = bcx + bc * vx - bs * vy;
            gyB[t] = bcy + bs * vx + bc * vy;
        }
#pragma unroll
        for (int t = 0; t < 4; t++) {
            float px = gxA[t] - bcx, py = gyA[t] - bcy;
            lxA[t] =  bc * px + bs * py;
            lyA[t] = -bs * px + bc * py;
            float qx = gxB[t] - acx, qy = gyB[t] - acy;
            lxB[t] =  ac * qx + as * qy;
            lyB[t] = -as * qx + ac * qy;
        }

        float cs = 0.f;
#pragma unroll
        for (int e = 0; e < 4; e++) {
            int e1 = (e + 1) & 3;
            cs += clip_contrib(gxA[e], gyA[e], gxA[e1], gyA[e1],
                               lxA[e], lyA[e], lxA[e1], lyA[e1], hbw, hbh);
        }
#pragma unroll
        for (int e = 0; e < 4; e++) {
            int e1 = (e + 1) & 3;
            cs += clip_contrib(gxB[e], gyB[e], gxB[e1], gyB[e1],
                               lxB[e], lyB[e], lxB[e1], lyB[e1], haw, hah);
        }

        float inter = 0.5f * fabsf(cs);
        float uni = aw * ah + bw * bh - inter;
        float iou = __fdividef(inter, fmaxf(uni, 1e-12f));
        iouv += 2.f * fmaxf(iou - 0.1f, 0.f);
    }

    // ---- deterministic fixed-order block reduction ----
    s1[tid] = repel; s2[tid] = iouv;
    __syncthreads();
#pragma unroll
    for (int off = TPB / 2; off > 0; off >>= 1) {
        if (tid < off) { s1[tid] += s1[tid + off]; s2[tid] += s2[tid + off]; }
        __syncthreads();
    }
    if (tid == 0) {
        g_partial[blockIdx.x][0] = s1[0];
        g_partial[blockIdx.x][1] = s2[0];
        __threadfence();
        int c = atomicAdd(&g_count, 1);
        last = (c == NBLK - 1);
    }
    __syncthreads();

    // ---- last-arriving block: fixed-order final combine + size loss ----
    if (last) {
        float r = 0.f, v = 0.f;
        for (int b = tid; b < NBLK; b += TPB) {
            r += g_partial[b][0];
            v += g_partial[b][1];
        }
        float pen = 0.f;
        for (int i = tid; i < M; i += TPB) {
            float w = spred[i * 6 + 2], h = spred[i * 6 + 3];
            pen += fmaxf(0.02f - w, 0.f) + fmaxf(0.02f - h, 0.f);
        }
        s1[tid] = r; s2[tid] = v; s3[tid] = pen;
        __syncthreads();
#pragma unroll
        for (int off = TPB / 2; off > 0; off >>= 1) {
            if (tid < off) {
                s1[tid] += s1[tid + off];
                s2[tid] += s2[tid + off];
                s3[tid] += s3[tid + off];
            }
            __syncthreads();
        }
        if (tid == 0) {
            float total = s1[0] / (float)(M * (M - 1))
                        + s3[0] / (float)M
                        + s2[0] / (float)(M * M);
            for (int o = 0; o < out_size; o++) out[o] = total;
            g_count = 0;   // re-arm for next graph replay
        }
    }
}

extern "C" void kernel_launch(void* const* d_in, const int* in_sizes, int n_in,
                              void* d_out, int out_size) {
    const float* pred = (const float*)d_in[0];
    float* out = (float*)d_out;
    fused_kernel<<<NBLK, TPB>>>(pred, out, out_size);
}

// round 10
// speedup vs baseline: 2.2350x; 1.1800x over previous
#include <cuda_runtime.h>
#include <math.h>

#define M      768
#define G      24            // groups of 32 boxes
#define NTP    300           // G*(G+1)/2 unordered group-pairs
#define NCHUNK (NTP * 2)     // split each tile-pair into 2 j-halves -> 600
#define WPB    4
#define TPB    (WPB * 32)    // 128
#define NBLK   (NCHUNK / WPB) // 150 blocks, 1 chunk per warp exactly
#define QCAP   512            // worst case 16 j-iters * 32 lanes

__device__ float g_partial[NBLK][2];
__device__ int   g_count;    // zero-init; re-armed by finalize

// Clip directed edge (global g0->g1; same edge in clipping box's local frame
// l0->l1) against |x|<=hw,|y|<=hh. Returns cross(pa,pb) of surviving segment
// in the GLOBAL frame; 0 if edge misses box.
__device__ __forceinline__ float clip_contrib(
    float g0x, float g0y, float g1x, float g1y,
    float l0x, float l0y, float l1x, float l1y,
    float hw, float hh)
{
    float tlo = 0.f, thi = 1.f;
    bool empty = false;
#define CLIP_PLANE(D0, D1)                              \
    {                                                   \
        float d0 = (D0), d1 = (D1);                     \
        bool o0 = d0 < 0.f, o1 = d1 < 0.f;              \
        empty = empty || (o0 && o1);                    \
        float t = __fdividef(d0, d0 - d1);              \
        if (o0) tlo = fmaxf(tlo, t);                    \
        if (o1) thi = fminf(thi, t);                    \
    }
    CLIP_PLANE(hw - l0x, hw - l1x)
    CLIP_PLANE(hw + l0x, hw + l1x)
    CLIP_PLANE(hh - l0y, hh - l1y)
    CLIP_PLANE(hh + l0y, hh + l1y)
#undef CLIP_PLANE
    if (empty || tlo >= thi) return 0.f;
    float ex = g1x - g0x, ey = g1y - g0y;
    float ax = g0x + tlo * ex, ay = g0y + tlo * ey;
    float bx = g0x + thi * ex, by = g0y + thi * ey;
    return ax * by - ay * bx;
}

// Exact rotated-rect IoU hinge for pair (i,j), boxes read from global (L2-hot).
__device__ __forceinline__ float iou_hinge(const float* __restrict__ pred,
                                           int i, int j)
{
    const float* pa = pred + i * 6;
    const float* pb = pred + j * 6;
    float acx = __ldg(pa + 0), acy = __ldg(pa + 1);
    float aw  = __ldg(pa + 2), ah  = __ldg(pa + 3);
    float ac  = __ldg(pa + 4), as  = __ldg(pa + 5);
    float bcx = __ldg(pb + 0), bcy = __ldg(pb + 1);
    float bw  = __ldg(pb + 2), bh  = __ldg(pb + 3);
    float bc  = __ldg(pb + 4), bs  = __ldg(pb + 5);

    float haw = 0.5f * aw, hah = 0.5f * ah;
    float hbw = 0.5f * bw, hbh = 0.5f * bh;

    float gxA[4], gyA[4], gxB[4], gyB[4];
    float lxA[4], lyA[4], lxB[4], lyB[4];
    const float SX[4] = {-1.f, 1.f, 1.f, -1.f};
    const float SY[4] = {-1.f, -1.f, 1.f, 1.f};
#pragma unroll
    for (int t = 0; t < 4; t++) {
        float ux = SX[t] * haw, uy = SY[t] * hah;
        gxA[t] = acx + ac * ux - as * uy;
        gyA[t] = acy + as * ux + ac * uy;
        float vx = SX[t] * hbw, vy = SY[t] * hbh;
        gxB[t] = bcx + bc * vx - bs * vy;
        gyB[t] = bcy + bs * vx + bc * vy;
    }
#pragma unroll
    for (int t = 0; t < 4; t++) {
        float px = gxA[t] - bcx, py = gyA[t] - bcy;
        lxA[t] =  bc * px + bs * py;
        lyA[t] = -bs * px + bc * py;
        float qx = gxB[t] - acx, qy = gyB[t] - acy;
        lxB[t] =  ac * qx + as * qy;
        lyB[t] = -as * qx + ac * qy;
    }
    float cs = 0.f;
#pragma unroll
    for (int e = 0; e < 4; e++) {
        int e1 = (e + 1) & 3;
        cs += clip_contrib(gxA[e], gyA[e], gxA[e1], gyA[e1],
                           lxA[e], lyA[e], lxA[e1], lyA[e1], hbw, hbh);
    }
#pragma unroll
    for (int e = 0; e < 4; e++) {
        int e1 = (e + 1) & 3;
        cs += clip_contrib(gxB[e], gyB[e], gxB[e1], gyB[e1],
                           lxB[e], lyB[e], lxB[e1], lyB[e1], haw, hah);
    }
    float inter = 0.5f * fabsf(cs);
    float uni = aw * ah + bw * bh - inter;
    float iou = __fdividef(inter, fmaxf(uni, 1e-12f));
    return 2.f * fmaxf(iou - 0.1f, 0.f);
}

__global__ __launch_bounds__(TPB)
void fused_kernel(const float* __restrict__ pred, float* __restrict__ out,
                  int out_size)
{
    __shared__ float4 jt[WPB][16];        // j-subtile: cx, cy, rad
    __shared__ int    q[WPB][QCAP];       // warp-private active-pair queue
    __shared__ float  sred[WPB * 2];
    __shared__ float  s1[TPB], s2[TPB], s3[TPB];
    __shared__ bool   last;

    const int tid  = threadIdx.x;
    const int wid  = tid >> 5;
    const int lane = tid & 31;

    // ---- decode chunk -> (gi, gj, j-half) ----
    int chunk = blockIdx.x * WPB + wid;   // 0..599, exactly one per warp
    int tp = chunk >> 1, jh = chunk & 1;
    int gi = 0, rem = tp;
    while (rem >= (G - gi)) { rem -= (G - gi); gi++; }
    int gj = gi + rem;

    // ---- lane's i-box (registers) ----
    int i = gi * 32 + lane;
    const float* pi = pred + i * 6;
    float icx = __ldg(pi + 0), icy = __ldg(pi + 1);
    float iw  = __ldg(pi + 2), ih  = __ldg(pi + 3);
    float irad = 0.5f * sqrtf(iw * iw + ih * ih);

    // ---- stage 16-box j-subtile (cx, cy, rad) to warp smem ----
    int jbase = gj * 32 + jh * 16;
    if (lane < 16) {
        const float* pj = pred + (jbase + lane) * 6;
        float w = __ldg(pj + 2), h = __ldg(pj + 3);
        jt[wid][lane] = make_float4(__ldg(pj + 0), __ldg(pj + 1),
                                    0.5f * sqrtf(w * w + h * h), 0.f);
    }
    __syncwarp();

    // ---- phase 1: 32 x 16 distance tests, repel, compact survivors ----
    float repel = 0.f;
    int qn = 0;
#pragma unroll
    for (int jj = 0; jj < 16; jj++) {
        float4 jb = jt[wid][jj];
        int j = jbase + jj;
        bool valid = i < j;    // gi<=gj makes this exactly "unordered pair"
        float dx = icx - jb.x, dy = icy - jb.y;
        float dist = sqrtf(dx * dx + dy * dy);
        if (valid) repel += 2.f * fmaxf(0.08f - dist, 0.f);
        bool act = valid && (dist < irad + jb.z);
        unsigned msk = __ballot_sync(0xFFFFFFFFu, act);
        if (act) {
            int rank = __popc(msk & ((1u << lane) - 1u));
            q[wid][qn + rank] = (i << 16) | j;
        }
        qn += __popc(msk);
    }
    __syncwarp();

    // ---- phase 2: drain queue at full lane utilization ----
    float iouv = 0.f;
    for (int base = 0; base < qn; base += 32) {
        int idx = base + lane;
        if (idx < qn) {
            int e = q[wid][idx];
            iouv += iou_hinge(pred, e >> 16, e & 0xFFFF);
        }
    }

    // ---- deterministic warp reduce (xor tree) ----
#pragma unroll
    for (int off = 16; off > 0; off >>= 1) {
        repel += __shfl_xor_sync(0xFFFFFFFFu, repel, off);
        iouv  += __shfl_xor_sync(0xFFFFFFFFu, iouv,  off);
    }
    if (lane == 0) { sred[wid * 2] = repel; sred[wid * 2 + 1] = iouv; }
    __syncthreads();

    if (tid == 0) {
        float r = 0.f, v = 0.f;
#pragma unroll
        for (int w = 0; w < WPB; w++) { r += sred[w * 2]; v += sred[w * 2 + 1]; }
        g_partial[blockIdx.x][0] = r;
        g_partial[blockIdx.x][1] = v;
        __threadfence();
        int c = atomicAdd(&g_count, 1);
        last = (c == NBLK - 1);
    }
    __syncthreads();

    // ---- last-arriving block: fixed-order final combine + size loss ----
    if (last) {
        float r = 0.f, v = 0.f;
        for (int b = tid; b < NBLK; b += TPB) {
            r += g_partial[b][0];
            v += g_partial[b][1];
        }
        float pen = 0.f;
        for (int bi = tid; bi < M; bi += TPB) {
            float w = __ldg(pred + bi * 6 + 2);
            float h = __ldg(pred + bi * 6 + 3);
            pen += fmaxf(0.02f - w, 0.f) + fmaxf(0.02f - h, 0.f);
        }
        s1[tid] = r; s2[tid] = v; s3[tid] = pen;
        __syncthreads();
#pragma unroll
        for (int off = TPB / 2; off > 0; off >>= 1) {
            if (tid < off) {
                s1[tid] += s1[tid + off];
                s2[tid] += s2[tid + off];
                s3[tid] += s3[tid + off];
            }
            __syncthreads();
        }
        if (tid == 0) {
            float total = s1[0] / (float)(M * (M - 1))
                        + s3[0] / (float)M
                        + s2[0] / (float)(M * M);
            for (int o = 0; o < out_size; o++) out[o] = total;
            g_count = 0;   // re-arm for next graph replay
        }
    }
}

extern "C" void kernel_launch(void* const* d_in, const int* in_sizes, int n_in,
                              void* d_out, int out_size) {
    const float* pred = (const float*)d_in[0];
    float* out = (float*)d_out;
    fused_kernel<<<NBLK, TPB>>>(pred, out, out_size);
}

// round 11
// speedup vs baseline: 2.6687x; 1.1940x over previous
#include <cuda_runtime.h>
#include <math.h>

#define M      768
#define G      24             // groups of 32 boxes
#define NTP    300            // G*(G+1)/2 unordered group-pairs
#define JSPLIT 4              // j-quarters of 8 boxes
#define NCHUNK (NTP * JSPLIT) // 1200 chunks = 1200 warps
#define WPB    8
#define TPB    (WPB * 32)     // 256
#define NBLK   (NCHUNK / WPB) // 150 blocks
#define QCAP   256            // worst case 8 j-iters * 32 lanes

__device__ float g_partial[NBLK][2];
__device__ int   g_count;     // zero-init; re-armed by finalize

// Clip directed edge (global g0->g1; same edge in clipping box's local frame
// l0->l1) against |x|<=hw,|y|<=hh. Returns cross(pa,pb) of surviving segment
// in the GLOBAL frame; 0 if edge misses box.
__device__ __forceinline__ float clip_contrib(
    float g0x, float g0y, float g1x, float g1y,
    float l0x, float l0y, float l1x, float l1y,
    float hw, float hh)
{
    float tlo = 0.f, thi = 1.f;
    bool empty = false;
#define CLIP_PLANE(D0, D1)                              \
    {                                                   \
        float d0 = (D0), d1 = (D1);                     \
        bool o0 = d0 < 0.f, o1 = d1 < 0.f;              \
        empty = empty || (o0 && o1);                    \
        float t = __fdividef(d0, d0 - d1);              \
        if (o0) tlo = fmaxf(tlo, t);                    \
        if (o1) thi = fminf(thi, t);                    \
    }
    CLIP_PLANE(hw - l0x, hw - l1x)
    CLIP_PLANE(hw + l0x, hw + l1x)
    CLIP_PLANE(hh - l0y, hh - l1y)
    CLIP_PLANE(hh + l0y, hh + l1y)
#undef CLIP_PLANE
    if (empty || tlo >= thi) return 0.f;
    float ex = g1x - g0x, ey = g1y - g0y;
    float ax = g0x + tlo * ex, ay = g0y + tlo * ey;
    float bx = g0x + thi * ex, by = g0y + thi * ey;
    return ax * by - ay * bx;
}

// Exact rotated-rect IoU hinge for pair (i,j); vectorized float2 loads.
__device__ __forceinline__ float iou_hinge(const float* __restrict__ pred,
                                           int i, int j)
{
    const float2* pa = (const float2*)(pred + i * 6);   // 8B-aligned (24B rows)
    const float2* pb = (const float2*)(pred + j * 6);
    float2 a0 = __ldg(pa), a1 = __ldg(pa + 1), a2 = __ldg(pa + 2);
    float2 b0 = __ldg(pb), b1 = __ldg(pb + 1), b2 = __ldg(pb + 2);
    float acx = a0.x, acy = a0.y, aw = a1.x, ah = a1.y, ac = a2.x, as = a2.y;
    float bcx = b0.x, bcy = b0.y, bw = b1.x, bh = b1.y, bc = b2.x, bs = b2.y;

    float haw = 0.5f * aw, hah = 0.5f * ah;
    float hbw = 0.5f * bw, hbh = 0.5f * bh;

    float gxA[4], gyA[4], gxB[4], gyB[4];
    float lxA[4], lyA[4], lxB[4], lyB[4];
    const float SX[4] = {-1.f, 1.f, 1.f, -1.f};
    const float SY[4] = {-1.f, -1.f, 1.f, 1.f};
#pragma unroll
    for (int t = 0; t < 4; t++) {
        float ux = SX[t] * haw, uy = SY[t] * hah;
        gxA[t] = acx + ac * ux - as * uy;
        gyA[t] = acy + as * ux + ac * uy;
        float vx = SX[t] * hbw, vy = SY[t] * hbh;
        gxB[t] = bcx + bc * vx - bs * vy;
        gyB[t] = bcy + bs * vx + bc * vy;
    }
#pragma unroll
    for (int t = 0; t < 4; t++) {
        float px = gxA[t] - bcx, py = gyA[t] - bcy;
        lxA[t] =  bc * px + bs * py;
        lyA[t] = -bs * px + bc * py;
        float qx = gxB[t] - acx, qy = gyB[t] - acy;
        lxB[t] =  ac * qx + as * qy;
        lyB[t] = -as * qx + ac * qy;
    }
    float cs = 0.f;
#pragma unroll
    for (int e = 0; e < 4; e++) {
        int e1 = (e + 1) & 3;
        cs += clip_contrib(gxA[e], gyA[e], gxA[e1], gyA[e1],
                           lxA[e], lyA[e], lxA[e1], lyA[e1], hbw, hbh);
    }
#pragma unroll
    for (int e = 0; e < 4; e++) {
        int e1 = (e + 1) & 3;
        cs += clip_contrib(gxB[e], gyB[e], gxB[e1], gyB[e1],
                           lxB[e], lyB[e], lxB[e1], lyB[e1], haw, hah);
    }
    float inter = 0.5f * fabsf(cs);
    float uni = aw * ah + bw * bh - inter;
    float iou = __fdividef(inter, fmaxf(uni, 1e-12f));
    return 2.f * fmaxf(iou - 0.1f, 0.f);
}

__global__ __launch_bounds__(TPB)
void fused_kernel(const float* __restrict__ pred, float* __restrict__ out,
                  int out_size)
{
    __shared__ float4 jt[WPB][8];         // j-subtile: cx, cy, rad
    __shared__ int    q[WPB][QCAP];       // warp-private active-pair queue
    __shared__ float  sred[WPB * 2];
    __shared__ float  s1[TPB], s2[TPB], s3[TPB];
    __shared__ bool   last;

    const int tid  = threadIdx.x;
    const int wid  = tid >> 5;
    const int lane = tid & 31;

    // ---- closed-form chunk decode -> (gi, gj, j-quarter) ----
    int chunk = blockIdx.x * WPB + wid;   // 0..1199
    int tp = chunk >> 2, js = chunk & 3;
    // largest gi with gi*(2G-gi+1)/2 <= tp  (quadratic formula + fixup)
    const float TGP1 = 2.f * G + 1.f;     // 49
    int gi = (int)floorf((TGP1 - sqrtf(TGP1 * TGP1 - 8.f * (float)tp)) * 0.5f);
    if (gi > 0 && gi * (2 * G - gi + 1) / 2 > tp) gi--;
    if ((gi + 1) * (2 * G - gi) / 2 <= tp) gi++;
    int gj = gi + (tp - gi * (2 * G - gi + 1) / 2);

    // ---- lane's i-box (registers, float2 loads) ----
    int i = gi * 32 + lane;
    const float2* pi2 = (const float2*)(pred + i * 6);
    float2 i0 = __ldg(pi2), i1 = __ldg(pi2 + 1);
    float icx = i0.x, icy = i0.y;
    float irad = 0.5f * sqrtf(i1.x * i1.x + i1.y * i1.y);

    // ---- stage 8-box j-subtile (cx, cy, rad) to warp smem ----
    int jbase = gj * 32 + js * 8;
    if (lane < 8) {
        const float2* pj2 = (const float2*)(pred + (jbase + lane) * 6);
        float2 j0 = __ldg(pj2), j1 = __ldg(pj2 + 1);
        jt[wid][lane] = make_float4(j0.x, j0.y,
                                    0.5f * sqrtf(j1.x * j1.x + j1.y * j1.y), 0.f);
    }
    __syncwarp();

    // ---- phase 1: 32 x 8 distance tests, repel, compact survivors ----
    float repel = 0.f;
    int qn = 0;
#pragma unroll
    for (int jj = 0; jj < 8; jj++) {
        float4 jb = jt[wid][jj];
        int j = jbase + jj;
        bool valid = i < j;    // gi<=gj makes this exactly "unordered pair"
        float dx = icx - jb.x, dy = icy - jb.y;
        float dist = sqrtf(dx * dx + dy * dy);
        if (valid) repel += 2.f * fmaxf(0.08f - dist, 0.f);
        bool act = valid && (dist < irad + jb.z);
        unsigned msk = __ballot_sync(0xFFFFFFFFu, act);
        if (act) {
            int rank = __popc(msk & ((1u << lane) - 1u));
            q[wid][qn + rank] = (i << 16) | j;
        }
        qn += __popc(msk);
    }
    __syncwarp();

    // ---- phase 2: drain queue at full lane utilization ----
    float iouv = 0.f;
    for (int base = 0; base < qn; base += 32) {
        int idx = base + lane;
        if (idx < qn) {
            int e = q[wid][idx];
            iouv += iou_hinge(pred, e >> 16, e & 0xFFFF);
        }
    }

    // ---- deterministic warp reduce (xor tree) ----
#pragma unroll
    for (int off = 16; off > 0; off >>= 1) {
        repel += __shfl_xor_sync(0xFFFFFFFFu, repel, off);
        iouv  += __shfl_xor_sync(0xFFFFFFFFu, iouv,  off);
    }
    if (lane == 0) { sred[wid * 2] = repel; sred[wid * 2 + 1] = iouv; }
    __syncthreads();

    if (tid == 0) {
        float r = 0.f, v = 0.f;
#pragma unroll
        for (int w = 0; w < WPB; w++) { r += sred[w * 2]; v += sred[w * 2 + 1]; }
        g_partial[blockIdx.x][0] = r;
        g_partial[blockIdx.x][1] = v;
        __threadfence();
        int c = atomicAdd(&g_count, 1);
        last = (c == NBLK - 1);
    }
    __syncthreads();

    // ---- last-arriving block: fixed-order final combine + size loss ----
    if (last) {
        float r = 0.f, v = 0.f;
        for (int b = tid; b < NBLK; b += TPB) {
            r += g_partial[b][0];
            v += g_partial[b][1];
        }
        float pen = 0.f;
        for (int bi = tid; bi < M; bi += TPB) {
            const float2* pw = (const float2*)(pred + bi * 6);
            float2 wh = __ldg(pw + 1);
            pen += fmaxf(0.02f - wh.x, 0.f) + fmaxf(0.02f - wh.y, 0.f);
        }
        s1[tid] = r; s2[tid] = v; s3[tid] = pen;
        __syncthreads();
#pragma unroll
        for (int off = TPB / 2; off > 0; off >>= 1) {
            if (tid < off) {
                s1[tid] += s1[tid + off];
                s2[tid] += s2[tid + off];
                s3[tid] += s3[tid + off];
            }
            __syncthreads();
        }
        if (tid == 0) {
            float total = s1[0] / (float)(M * (M - 1))
                        + s3[0] / (float)M
                        + s2[0] / (float)(M * M);
            for (int o = 0; o < out_size; o++) out[o] = total;
            g_count = 0;   // re-arm for next graph replay
        }
    }
}

extern "C" void kernel_launch(void* const* d_in, const int* in_sizes, int n_in,
                              void* d_out, int out_size) {
    const float* pred = (const float*)d_in[0];
    float* out = (float*)d_out;
    fused_kernel<<<NBLK, TPB>>>(pred, out, out_size);
}